// round 14
// baseline (speedup 1.0000x reference)
#include <cuda_runtime.h>

using u64 = unsigned long long;

// ---------------- problem constants (fixed shapes) -------------------------
constexpr int Bn = 4;
constexpr int Nn = 8192;
constexpr int Cc = 32;
constexpr int M2 = 8192;
constexpr int M3 = 4096;
constexpr int M4 = 2048;
constexpr int MM = 4096;

constexpr int Q     = 4;           // queries per lane
constexpr int QPB   = 128;         // queries per block (32 lanes * Q)
constexpr int PARTS = 8;           // warps per block (candidate partitions)
constexpr int NT    = 256;
constexpr float BIG = 3.0e38f;

// ---------------- device scratch --------------------------------------------
// geometry records per 4-cand group: [x4|y4|z4|kk4] = 64 B
__device__ __align__(16) float g2buf[Bn * M2 * 4];
__device__ __align__(16) float g3buf[Bn * M3 * 4];
__device__ __align__(16) float g4buf[Bn * M4 * 4];
__device__ __align__(16) float gmbuf[Bn * MM * 4];
// fv payloads: flat per-element; group g owns [4g..4g+3] (float4-loadable)
__device__ __align__(16) float fv2buf[Bn * M2];
__device__ __align__(16) float fv3buf[Bn * M3];
__device__ __align__(16) float fv4buf[Bn * M4];

// ---------------- packed f32x2 helpers --------------------------------------
__device__ __forceinline__ u64 ffma2u(u64 a, u64 b, u64 c) {
    u64 r;
    asm("fma.rn.f32x2 %0, %1, %2, %3;" : "=l"(r) : "l"(a), "l"(b), "l"(c));
    return r;
}
__device__ __forceinline__ u64 fadd2u(u64 a, u64 b) {
    u64 r;
    asm("add.rn.f32x2 %0, %1, %2;" : "=l"(r) : "l"(a), "l"(b));
    return r;
}
__device__ __forceinline__ float lo_(u64 v) { return __uint_as_float((unsigned)v); }
__device__ __forceinline__ float hi_(u64 v) { return __uint_as_float((unsigned)(v >> 32)); }
__device__ __forceinline__ u64 dup2(float x) {
    unsigned b = __float_as_uint(x);
    return ((u64)b << 32) | (u64)b;
}

// ---------------- precompute: pack records + fv ------------------------------
__global__ void precompute_kernel(
    const float* __restrict__ known2, const float* __restrict__ feats2,
    const float* __restrict__ known3, const float* __restrict__ feats3,
    const float* __restrict__ known4, const float* __restrict__ feats4,
    const float* __restrict__ matchp,
    const float* __restrict__ w_fc, const float* __restrict__ w_cls)
{
    __shared__ float sv[96];                    // v = w_cls @ w_fc (per-block)
    int t = threadIdx.x;
    if (t < 96) {
        float acc = 0.f;
#pragma unroll
        for (int k = 0; k < 64; k++) acc = fmaf(w_cls[k], w_fc[k * 96 + t], acc);
        sv[t] = acc;
    }
    __syncthreads();

    int idx = blockIdx.x * NT + t;
    constexpr int A = Bn * M2;
    constexpr int B = A + Bn * M3;
    constexpr int C = B + Bn * M4;
    constexpr int D = C + Bn * MM;

    const float* known; const float* feats; float* buf; float* fvb; int i, voff;
    if (idx < A)      { known = known2; feats = feats2; buf = g2buf; fvb = fv2buf; i = idx;     voff = 0;  }
    else if (idx < B) { known = known3; feats = feats3; buf = g3buf; fvb = fv3buf; i = idx - A; voff = 32; }
    else if (idx < C) { known = known4; feats = feats4; buf = g4buf; fvb = fv4buf; i = idx - B; voff = 64; }
    else if (idx < D) {
        int i2 = idx - C;
        float x = matchp[3 * i2 + 0];
        float y = matchp[3 * i2 + 1];
        float z = matchp[3 * i2 + 2];
        float kk = __fadd_rn(__fadd_rn(__fmul_rn(x, x), __fmul_rn(y, y)), __fmul_rn(z, z));
        int base = (i2 >> 2) * 16 + (i2 & 3);
        gmbuf[base + 0] = x; gmbuf[base + 4] = y;
        gmbuf[base + 8] = z; gmbuf[base + 12] = kk;
        return;
    } else return;

    float x = known[3 * i + 0];
    float y = known[3 * i + 1];
    float z = known[3 * i + 2];
    // same rounding order as jnp.sum(known*known, -1)
    float kk = __fadd_rn(__fadd_rn(__fmul_rn(x, x), __fmul_rn(y, y)), __fmul_rn(z, z));

    float acc = 0.f;
    const float4* f4 = reinterpret_cast<const float4*>(feats + (size_t)i * Cc);
#pragma unroll
    for (int j = 0; j < 8; j++) {
        float4 tt = f4[j];
        acc = fmaf(tt.x, sv[voff + 4 * j + 0], acc);
        acc = fmaf(tt.y, sv[voff + 4 * j + 1], acc);
        acc = fmaf(tt.z, sv[voff + 4 * j + 2], acc);
        acc = fmaf(tt.w, sv[voff + 4 * j + 3], acc);
    }
    int base = (i >> 2) * 16 + (i & 3);
    buf[base + 0]  = x;  buf[base + 4]  = y;
    buf[base + 8]  = z;  buf[base + 12] = kk;
    fvb[i] = acc;
}

// ---------------- top-3 maintenance ------------------------------------------
__device__ __forceinline__ void try_ins(float e, float fv, float t[3], float f[3]) {
    if (e < t[2]) {
        if (e < t[1]) {
            t[2] = t[1]; f[2] = f[1];
            if (e < t[0]) { t[1] = t[0]; f[1] = f[0]; t[0] = e; f[0] = fv; }
            else          { t[1] = e;    f[1] = fv; }
        } else { t[2] = e; f[2] = fv; }
    }
}
// caller guarantees e < m[2]
__device__ __forceinline__ void try_ins_g(float e, int g, float m[3], int gi[3]) {
    if (e < m[1]) {
        m[2] = m[1]; gi[2] = gi[1];
        if (e < m[0]) { m[1] = m[0]; gi[1] = gi[0]; m[0] = e; gi[0] = g; }
        else          { m[1] = e;    gi[1] = g; }
    } else { m[2] = e; gi[2] = g; }
}

// packed distances of one 64B group record; reference rounding order
__device__ __forceinline__ void group_d(const float* buf, int g,
    u64 c2x, u64 c2y, u64 c2z, u64 qq2,
    float& d0, float& d1, float& d2, float& d3)
{
    const char* p = reinterpret_cast<const char*>(buf) + (size_t)g * 64;
    ulonglong2 X = __ldg(reinterpret_cast<const ulonglong2*>(p));
    ulonglong2 Y = __ldg(reinterpret_cast<const ulonglong2*>(p + 16));
    ulonglong2 Z = __ldg(reinterpret_cast<const ulonglong2*>(p + 32));
    ulonglong2 W = __ldg(reinterpret_cast<const ulonglong2*>(p + 48));
    u64 dl = fadd2u(qq2, W.x);
    dl = ffma2u(c2x, X.x, dl); dl = ffma2u(c2y, Y.x, dl); dl = ffma2u(c2z, Z.x, dl);
    u64 dh = fadd2u(qq2, W.y);
    dh = ffma2u(c2x, X.y, dh); dh = ffma2u(c2y, Y.y, dh); dh = ffma2u(c2z, Z.y, dh);
    d0 = lo_(dl); d1 = hi_(dl); d2 = lo_(dh); d3 = hi_(dh);
}

// ---------------- interp scan: group-min top-3 + exact rescan -----------------
__device__ __forceinline__ void scan_set(
    const float* __restrict__ buf, const float* __restrict__ fvb,
    int grp0, int Mg,
    const u64 c2x[Q], const u64 c2y[Q], const u64 c2z[Q], const u64 qq2[Q],
    float t[Q][3], float f[Q][3])
{
    float m[Q][3]; int gi[Q][3];
#pragma unroll
    for (int j = 0; j < Q; j++) {
        m[j][0] = m[j][1] = m[j][2] = BIG;
        gi[j][0] = gi[j][1] = gi[j][2] = -1;
    }
    const char* p = reinterpret_cast<const char*>(buf) + (size_t)grp0 * 64;
#pragma unroll 2
    for (int g = grp0; g < grp0 + Mg; g++, p += 64) {
        ulonglong2 X = __ldg(reinterpret_cast<const ulonglong2*>(p));
        ulonglong2 Y = __ldg(reinterpret_cast<const ulonglong2*>(p + 16));
        ulonglong2 Z = __ldg(reinterpret_cast<const ulonglong2*>(p + 32));
        ulonglong2 W = __ldg(reinterpret_cast<const ulonglong2*>(p + 48));
#pragma unroll
        for (int j = 0; j < Q; j++) {
            u64 dl = fadd2u(qq2[j], W.x);
            dl = ffma2u(c2x[j], X.x, dl);
            dl = ffma2u(c2y[j], Y.x, dl);
            dl = ffma2u(c2z[j], Z.x, dl);
            u64 dh = fadd2u(qq2[j], W.y);
            dh = ffma2u(c2x[j], X.y, dh);
            dh = ffma2u(c2y[j], Y.y, dh);
            dh = ffma2u(c2z[j], Z.y, dh);
            float mm = fminf(fminf(lo_(dl), hi_(dl)), fminf(lo_(dh), hi_(dh)));
            if (mm < m[j][2]) try_ins_g(mm, g, m[j], gi[j]);   // single insert
        }
    }

    // exact rescan of the <=3 winning groups per query (bit-identical math)
    const float4* fv4 = reinterpret_cast<const float4*>(fvb);
#pragma unroll
    for (int j = 0; j < Q; j++) {
        t[j][0] = t[j][1] = t[j][2] = BIG;
        f[j][0] = f[j][1] = f[j][2] = 0.f;
#pragma unroll
        for (int k = 0; k < 3; k++) {
            int gg = gi[j][k];
            if (gg >= 0) {
                float d0, d1, d2, d3;
                group_d(buf, gg, c2x[j], c2y[j], c2z[j], qq2[j], d0, d1, d2, d3);
                float4 F = __ldg(fv4 + gg);
                try_ins(d0, F.x, t[j], f[j]);
                try_ins(d1, F.y, t[j], f[j]);
                try_ins(d2, F.z, t[j], f[j]);
                try_ins(d3, F.w, t[j], f[j]);
            }
        }
    }
}

// ---------------- mask scan: any(d2 < 0.25), margin + exact recheck -----------
__device__ __forceinline__ void scan_mask(
    const float* __restrict__ buf, int grp0, int Mg,
    const u64 c2x[Q], const u64 c2y[Q], const u64 c2z[Q], const u64 qq2[Q],
    bool found[Q])
{
    float tf[Q], qx[Q], qy[Q], qz[Q], qqv[Q];
#pragma unroll
    for (int j = 0; j < Q; j++) {
        found[j] = false;
        qqv[j] = lo_(qq2[j]);
        tf[j]  = 0.3125f - qqv[j];               // e < 0.25 + 0.0625 margin
        qx[j]  = -0.5f * lo_(c2x[j]);            // exact (pow2 scale)
        qy[j]  = -0.5f * lo_(c2y[j]);
        qz[j]  = -0.5f * lo_(c2z[j]);
    }
    const char* p = reinterpret_cast<const char*>(buf) + (size_t)grp0 * 64;
#pragma unroll 2
    for (int g = 0; g < Mg; g++, p += 64) {
        ulonglong2 X = __ldg(reinterpret_cast<const ulonglong2*>(p));
        ulonglong2 Y = __ldg(reinterpret_cast<const ulonglong2*>(p + 16));
        ulonglong2 Z = __ldg(reinterpret_cast<const ulonglong2*>(p + 32));
        ulonglong2 W = __ldg(reinterpret_cast<const ulonglong2*>(p + 48));
#pragma unroll
        for (int j = 0; j < Q; j++) {
            // fast path: e = kk - 2*dot (qq deferred; protected by margin)
            u64 el = ffma2u(c2x[j], X.x, ffma2u(c2y[j], Y.x, ffma2u(c2z[j], Z.x, W.x)));
            u64 eh = ffma2u(c2x[j], X.y, ffma2u(c2y[j], Y.y, ffma2u(c2z[j], Z.y, W.y)));
            float mm = fminf(fminf(lo_(el), hi_(el)), fminf(lo_(eh), hi_(eh)));
            if (mm < tf[j]) {                     // rare: exact recheck
                float cx[4] = { lo_(X.x), hi_(X.x), lo_(X.y), hi_(X.y) };
                float cy[4] = { lo_(Y.x), hi_(Y.x), lo_(Y.y), hi_(Y.y) };
                float cz[4] = { lo_(Z.x), hi_(Z.x), lo_(Z.y), hi_(Z.y) };
                float cw[4] = { lo_(W.x), hi_(W.x), lo_(W.y), hi_(W.y) };
#pragma unroll
                for (int c = 0; c < 4; c++) {
                    // bit-exact reference-mimic rounding
                    float dot = __fadd_rn(__fadd_rn(__fmul_rn(qx[j], cx[c]),
                                                    __fmul_rn(qy[j], cy[c])),
                                          __fmul_rn(qz[j], cz[c]));
                    float d = __fsub_rn(__fadd_rn(qqv[j], cw[c]),
                                        __fadd_rn(dot, dot));
                    if (d < 0.25f) found[j] = true;
                }
            }
        }
    }
}

// ---------------- merge 24 partial top-3 entries -------------------------------
__device__ __forceinline__ float merge_one(const float2* __restrict__ ent) {
    float t[3] = {BIG, BIG, BIG}, f[3] = {0.f, 0.f, 0.f};
#pragma unroll
    for (int k = 0; k < PARTS * 3; k++) {
        float2 c = ent[k];
        try_ins(c.x, c.y, t, f);
    }
    float d0 = fmaxf(t[0], 0.f);
    float d1 = fmaxf(t[1], 0.f);
    float d2 = fmaxf(t[2], 0.f);
    float r0 = 1.f / (d0 + 1e-8f);
    float r1 = 1.f / (d1 + 1e-8f);
    float r2 = 1.f / (d2 + 1e-8f);
    return fmaf(r0, f[0], fmaf(r1, f[1], r2 * f[2])) / (r0 + r1 + r2);
}

// ---------------- fused main kernel ---------------------------------------------
// grid = 256 blocks; with <=85 regs 3 blocks/SM capacity: all co-resident
__global__ void __launch_bounds__(NT, 3)
fused_kernel(const float* __restrict__ pts, float* __restrict__ out) {
    __shared__ float2 s_m[QPB * PARTS * 3];      // 24 KB merge scratch

    const int tid   = threadIdx.x;
    const int qslot = tid & 31;                  // lane
    const int part  = tid >> 5;                  // warp id == candidate part
    const int b     = (blockIdx.x * QPB) >> 13;  // batch (64 blocks per batch)

    u64 c2x[Q], c2y[Q], c2z[Q], qq2[Q];
#pragma unroll
    for (int j = 0; j < Q; j++) {
        int gq = blockIdx.x * QPB + Q * qslot + j;
        float x = pts[3 * gq + 0];
        float y = pts[3 * gq + 1];
        float z = pts[3 * gq + 2];
        float qq = __fadd_rn(__fadd_rn(__fmul_rn(x, x), __fmul_rn(y, y)),
                             __fmul_rn(z, z));
        c2x[j] = dup2(-2.f * x);
        c2y[j] = dup2(-2.f * y);
        c2z[j] = dup2(-2.f * z);
        qq2[j] = dup2(qq);
    }

    float pred = 0.f;                            // meaningful for tid < QPB
    float t[Q][3], f[Q][3];

    const float* sb[3]  = { g2buf, g3buf, g4buf };
    const float* sfv[3] = { fv2buf, fv3buf, fv4buf };
    const int    sM[3]  = { M2, M3, M4 };

#pragma unroll 1
    for (int s = 0; s < 3; s++) {
        const int Mg = sM[s] / (4 * PARTS);      // groups per part
        const int grp0 = (b * sM[s]) / 4 + part * Mg;
        scan_set(sb[s], sfv[s], grp0, Mg, c2x, c2y, c2z, qq2, t, f);
#pragma unroll
        for (int j = 0; j < Q; j++) {
            int q = Q * qslot + j;
            int bse = (q * PARTS + part) * 3;
            s_m[bse + 0] = make_float2(t[j][0], f[j][0]);
            s_m[bse + 1] = make_float2(t[j][1], f[j][1]);
            s_m[bse + 2] = make_float2(t[j][2], f[j][2]);
        }
        __syncthreads();
        if (tid < QPB) pred += merge_one(s_m + tid * PARTS * 3);
        __syncthreads();
    }

    bool found[Q];
    {
        const int Mg = MM / (4 * PARTS);
        const int grp0 = (b * MM) / 4 + part * Mg;
        scan_mask(gmbuf, grp0, Mg, c2x, c2y, c2z, qq2, found);
    }

    float* s_fl = reinterpret_cast<float*>(s_m);
#pragma unroll
    for (int j = 0; j < Q; j++)
        s_fl[(Q * qslot + j) * PARTS + part] = found[j] ? 1.f : 0.f;
    __syncthreads();
    if (tid < QPB) {
        float fl = 0.f;
#pragma unroll
        for (int k = 0; k < PARTS; k++) fl = fmaxf(fl, s_fl[tid * PARTS + k]);
        int gq = blockIdx.x * QPB + tid;
        out[gq] = pred;                          // pred_hm (B,N,1)
        out[Bn * Nn + gq] = fl;                  // gt_hm   (B,N)
    }
}

// ---------------- launch ----------------------------------------------------------
extern "C" void kernel_launch(void* const* d_in, const int* in_sizes, int n_in,
                              void* d_out, int out_size) {
    (void)in_sizes; (void)n_in; (void)out_size;
    const float* pts    = (const float*)d_in[0];
    const float* known2 = (const float*)d_in[1];
    const float* feats2 = (const float*)d_in[2];
    const float* known3 = (const float*)d_in[3];
    const float* feats3 = (const float*)d_in[4];
    const float* known4 = (const float*)d_in[5];
    const float* feats4 = (const float*)d_in[6];
    const float* matchp = (const float*)d_in[7];
    const float* w_fc   = (const float*)d_in[8];
    const float* w_cls  = (const float*)d_in[9];
    float* out = (float*)d_out;

    constexpr int total = Bn * (M2 + M3 + M4 + MM);
    precompute_kernel<<<(total + NT - 1) / NT, NT>>>(
        known2, feats2, known3, feats3, known4, feats4, matchp, w_fc, w_cls);
    fused_kernel<<<(Bn * Nn) / QPB, NT>>>(pts, out);
}

// round 15
// speedup vs baseline: 1.0389x; 1.0389x over previous
#include <cuda_runtime.h>

using u64 = unsigned long long;

// ---------------- problem constants (fixed shapes) -------------------------
constexpr int Bn = 4;
constexpr int Nn = 8192;
constexpr int Cc = 32;
constexpr int M2 = 8192;
constexpr int M3 = 4096;
constexpr int M4 = 2048;
constexpr int MM = 4096;

constexpr int Q     = 2;           // queries per lane
constexpr int QPB   = 64;          // queries per block (32 lanes * Q)
constexpr int PARTS = 8;           // warps per block (candidate partitions)
constexpr int NT    = 256;
constexpr float BIG = 3.0e38f;

// ---------------- device scratch --------------------------------------------
// geometry records per 4-cand group: [x4|y4|z4|kk4] = 64 B
__device__ __align__(16) float g2buf[Bn * M2 * 4];
__device__ __align__(16) float g3buf[Bn * M3 * 4];
__device__ __align__(16) float g4buf[Bn * M4 * 4];
__device__ __align__(16) float gmbuf[Bn * MM * 4];
// fv payloads: flat per-element; group g owns [4g..4g+3] (float4-loadable)
__device__ __align__(16) float fv2buf[Bn * M2];
__device__ __align__(16) float fv3buf[Bn * M3];
__device__ __align__(16) float fv4buf[Bn * M4];

// ---------------- packed f32x2 helpers --------------------------------------
__device__ __forceinline__ u64 ffma2u(u64 a, u64 b, u64 c) {
    u64 r;
    asm("fma.rn.f32x2 %0, %1, %2, %3;" : "=l"(r) : "l"(a), "l"(b), "l"(c));
    return r;
}
__device__ __forceinline__ u64 fadd2u(u64 a, u64 b) {
    u64 r;
    asm("add.rn.f32x2 %0, %1, %2;" : "=l"(r) : "l"(a), "l"(b));
    return r;
}
__device__ __forceinline__ float lo_(u64 v) { return __uint_as_float((unsigned)v); }
__device__ __forceinline__ float hi_(u64 v) { return __uint_as_float((unsigned)(v >> 32)); }
__device__ __forceinline__ u64 dup2(float x) {
    unsigned b = __float_as_uint(x);
    return ((u64)b << 32) | (u64)b;
}

// ---------------- precompute: pack records + fv ------------------------------
__global__ void precompute_kernel(
    const float* __restrict__ known2, const float* __restrict__ feats2,
    const float* __restrict__ known3, const float* __restrict__ feats3,
    const float* __restrict__ known4, const float* __restrict__ feats4,
    const float* __restrict__ matchp,
    const float* __restrict__ w_fc, const float* __restrict__ w_cls)
{
    __shared__ float sv[96];                    // v = w_cls @ w_fc (per-block)
    int t = threadIdx.x;
    if (t < 96) {
        float acc = 0.f;
#pragma unroll
        for (int k = 0; k < 64; k++) acc = fmaf(w_cls[k], w_fc[k * 96 + t], acc);
        sv[t] = acc;
    }
    __syncthreads();

    int idx = blockIdx.x * NT + t;
    constexpr int A = Bn * M2;
    constexpr int B = A + Bn * M3;
    constexpr int C = B + Bn * M4;
    constexpr int D = C + Bn * MM;

    const float* known; const float* feats; float* buf; float* fvb; int i, voff;
    if (idx < A)      { known = known2; feats = feats2; buf = g2buf; fvb = fv2buf; i = idx;     voff = 0;  }
    else if (idx < B) { known = known3; feats = feats3; buf = g3buf; fvb = fv3buf; i = idx - A; voff = 32; }
    else if (idx < C) { known = known4; feats = feats4; buf = g4buf; fvb = fv4buf; i = idx - B; voff = 64; }
    else if (idx < D) {
        int i2 = idx - C;
        float x = matchp[3 * i2 + 0];
        float y = matchp[3 * i2 + 1];
        float z = matchp[3 * i2 + 2];
        float kk = __fadd_rn(__fadd_rn(__fmul_rn(x, x), __fmul_rn(y, y)), __fmul_rn(z, z));
        int base = (i2 >> 2) * 16 + (i2 & 3);
        gmbuf[base + 0] = x; gmbuf[base + 4] = y;
        gmbuf[base + 8] = z; gmbuf[base + 12] = kk;
        return;
    } else return;

    float x = known[3 * i + 0];
    float y = known[3 * i + 1];
    float z = known[3 * i + 2];
    // same rounding order as jnp.sum(known*known, -1)
    float kk = __fadd_rn(__fadd_rn(__fmul_rn(x, x), __fmul_rn(y, y)), __fmul_rn(z, z));

    float acc = 0.f;
    const float4* f4 = reinterpret_cast<const float4*>(feats + (size_t)i * Cc);
#pragma unroll
    for (int j = 0; j < 8; j++) {
        float4 tt = f4[j];
        acc = fmaf(tt.x, sv[voff + 4 * j + 0], acc);
        acc = fmaf(tt.y, sv[voff + 4 * j + 1], acc);
        acc = fmaf(tt.z, sv[voff + 4 * j + 2], acc);
        acc = fmaf(tt.w, sv[voff + 4 * j + 3], acc);
    }
    int base = (i >> 2) * 16 + (i & 3);
    buf[base + 0]  = x;  buf[base + 4]  = y;
    buf[base + 8]  = z;  buf[base + 12] = kk;
    fvb[i] = acc;
}

// ---------------- top-3 maintenance ------------------------------------------
__device__ __forceinline__ void try_ins(float e, float fv, float t[3], float f[3]) {
    if (e < t[2]) {
        if (e < t[1]) {
            t[2] = t[1]; f[2] = f[1];
            if (e < t[0]) { t[1] = t[0]; f[1] = f[0]; t[0] = e; f[0] = fv; }
            else          { t[1] = e;    f[1] = fv; }
        } else { t[2] = e; f[2] = fv; }
    }
}
// caller guarantees e < m[2]
__device__ __forceinline__ void try_ins_g(float e, int g, float m[3], int gi[3]) {
    if (e < m[1]) {
        m[2] = m[1]; gi[2] = gi[1];
        if (e < m[0]) { m[1] = m[0]; gi[1] = gi[0]; m[0] = e; gi[0] = g; }
        else          { m[1] = e;    gi[1] = g; }
    } else { m[2] = e; gi[2] = g; }
}

// packed distances of one 64B group record; reference rounding order
__device__ __forceinline__ void group_d(const float* buf, int g,
    u64 c2x, u64 c2y, u64 c2z, u64 qq2,
    float& d0, float& d1, float& d2, float& d3)
{
    const ulonglong2* P = reinterpret_cast<const ulonglong2*>(buf) + (size_t)g * 4;
    ulonglong2 X = __ldg(P + 0);
    ulonglong2 Y = __ldg(P + 1);
    ulonglong2 Z = __ldg(P + 2);
    ulonglong2 W = __ldg(P + 3);
    u64 dl = fadd2u(qq2, W.x);
    dl = ffma2u(c2x, X.x, dl); dl = ffma2u(c2y, Y.x, dl); dl = ffma2u(c2z, Z.x, dl);
    u64 dh = fadd2u(qq2, W.y);
    dh = ffma2u(c2x, X.y, dh); dh = ffma2u(c2y, Y.y, dh); dh = ffma2u(c2z, Z.y, dh);
    d0 = lo_(dl); d1 = hi_(dl); d2 = lo_(dh); d3 = hi_(dh);
}

// ---------------- interp scan: group-min top-3 + exact rescan -----------------
// prefetched loads + single fused gate region per group
__device__ __forceinline__ void scan_set(
    const float* __restrict__ buf, const float* __restrict__ fvb,
    int grp0, int Mg,
    const u64 c2x[Q], const u64 c2y[Q], const u64 c2z[Q], const u64 qq2[Q],
    float t[Q][3], float f[Q][3])
{
    float m[Q][3]; int gi[Q][3];
#pragma unroll
    for (int j = 0; j < Q; j++) {
        m[j][0] = m[j][1] = m[j][2] = BIG;
        gi[j][0] = gi[j][1] = gi[j][2] = -1;
    }
    const ulonglong2* P = reinterpret_cast<const ulonglong2*>(buf) + (size_t)grp0 * 4;
    ulonglong2 X = __ldg(P + 0);
    ulonglong2 Y = __ldg(P + 1);
    float m2max = BIG;
    const int gend = grp0 + Mg;
#pragma unroll 2
    for (int g = grp0; g < gend; g++) {
        ulonglong2 Z = __ldg(P + 2);
        ulonglong2 W = __ldg(P + 3);
        const ulonglong2* Pn = P + ((g + 1 < gend) ? 4 : 0);   // clamped prefetch
        ulonglong2 Xn = __ldg(Pn + 0);
        ulonglong2 Yn = __ldg(Pn + 1);
        float mm[Q];
#pragma unroll
        for (int j = 0; j < Q; j++) {
            u64 dl = fadd2u(qq2[j], W.x);
            dl = ffma2u(c2x[j], X.x, dl);
            dl = ffma2u(c2y[j], Y.x, dl);
            dl = ffma2u(c2z[j], Z.x, dl);
            u64 dh = fadd2u(qq2[j], W.y);
            dh = ffma2u(c2x[j], X.y, dh);
            dh = ffma2u(c2y[j], Y.y, dh);
            dh = ffma2u(c2z[j], Z.y, dh);
            mm[j] = fminf(fminf(lo_(dl), hi_(dl)), fminf(lo_(dh), hi_(dh)));
        }
        if (fminf(mm[0], mm[1]) < m2max) {       // one branch region per group
            if (mm[0] < m[0][2]) try_ins_g(mm[0], g, m[0], gi[0]);
            if (mm[1] < m[1][2]) try_ins_g(mm[1], g, m[1], gi[1]);
            m2max = fmaxf(m[0][2], m[1][2]);
        }
        X = Xn; Y = Yn; P = Pn;
    }

    // exact rescan of the <=3 winning groups per query (bit-identical math)
    const float4* fv4 = reinterpret_cast<const float4*>(fvb);
#pragma unroll
    for (int j = 0; j < Q; j++) {
        t[j][0] = t[j][1] = t[j][2] = BIG;
        f[j][0] = f[j][1] = f[j][2] = 0.f;
#pragma unroll
        for (int k = 0; k < 3; k++) {
            int gg = gi[j][k];
            if (gg >= 0) {
                float d0, d1, d2, d3;
                group_d(buf, gg, c2x[j], c2y[j], c2z[j], qq2[j], d0, d1, d2, d3);
                float4 F = __ldg(fv4 + gg);
                try_ins(d0, F.x, t[j], f[j]);
                try_ins(d1, F.y, t[j], f[j]);
                try_ins(d2, F.z, t[j], f[j]);
                try_ins(d3, F.w, t[j], f[j]);
            }
        }
    }
}

// ---------------- mask scan: any(d2 < 0.25), margin + exact recheck -----------
__device__ __forceinline__ void scan_mask(
    const float* __restrict__ buf, int grp0, int Mg,
    const u64 c2x[Q], const u64 c2y[Q], const u64 c2z[Q], const u64 qq2[Q],
    bool found[Q])
{
    float tf[Q], qx[Q], qy[Q], qz[Q], qqv[Q];
#pragma unroll
    for (int j = 0; j < Q; j++) {
        found[j] = false;
        qqv[j] = lo_(qq2[j]);
        tf[j]  = 0.3125f - qqv[j];               // e < 0.25 + 0.0625 margin
        qx[j]  = -0.5f * lo_(c2x[j]);            // exact (pow2 scale)
        qy[j]  = -0.5f * lo_(c2y[j]);
        qz[j]  = -0.5f * lo_(c2z[j]);
    }
    const ulonglong2* P = reinterpret_cast<const ulonglong2*>(buf) + (size_t)grp0 * 4;
    const int gend = grp0 + Mg;
#pragma unroll 2
    for (int g = grp0; g < gend; g++) {
        ulonglong2 X = __ldg(P + 0);
        ulonglong2 Y = __ldg(P + 1);
        ulonglong2 Z = __ldg(P + 2);
        ulonglong2 W = __ldg(P + 3);
        P += 4;
        float mm[Q];
#pragma unroll
        for (int j = 0; j < Q; j++) {
            // fast path: e = kk - 2*dot (qq deferred; protected by margin)
            u64 el = ffma2u(c2x[j], X.x, ffma2u(c2y[j], Y.x, ffma2u(c2z[j], Z.x, W.x)));
            u64 eh = ffma2u(c2x[j], X.y, ffma2u(c2y[j], Y.y, ffma2u(c2z[j], Z.y, W.y)));
            mm[j] = fminf(fminf(lo_(el), hi_(el)), fminf(lo_(eh), hi_(eh)));
        }
        if ((mm[0] < tf[0]) || (mm[1] < tf[1])) {   // single rare gate
            float cx[4] = { lo_(X.x), hi_(X.x), lo_(X.y), hi_(X.y) };
            float cy[4] = { lo_(Y.x), hi_(Y.x), lo_(Y.y), hi_(Y.y) };
            float cz[4] = { lo_(Z.x), hi_(Z.x), lo_(Z.y), hi_(Z.y) };
            float cw[4] = { lo_(W.x), hi_(W.x), lo_(W.y), hi_(W.y) };
#pragma unroll
            for (int j = 0; j < Q; j++) {
                if (mm[j] < tf[j]) {
#pragma unroll
                    for (int c = 0; c < 4; c++) {
                        // bit-exact reference-mimic rounding
                        float dot = __fadd_rn(__fadd_rn(__fmul_rn(qx[j], cx[c]),
                                                        __fmul_rn(qy[j], cy[c])),
                                              __fmul_rn(qz[j], cz[c]));
                        float d = __fsub_rn(__fadd_rn(qqv[j], cw[c]),
                                            __fadd_rn(dot, dot));
                        if (d < 0.25f) found[j] = true;
                    }
                }
            }
        }
    }
}

// ---------------- merge 24 partial top-3 entries -------------------------------
__device__ __forceinline__ float merge_one(const float2* __restrict__ ent) {
    float t[3] = {BIG, BIG, BIG}, f[3] = {0.f, 0.f, 0.f};
#pragma unroll
    for (int k = 0; k < PARTS * 3; k++) {
        float2 c = ent[k];
        try_ins(c.x, c.y, t, f);
    }
    float d0 = fmaxf(t[0], 0.f);
    float d1 = fmaxf(t[1], 0.f);
    float d2 = fmaxf(t[2], 0.f);
    float r0 = 1.f / (d0 + 1e-8f);
    float r1 = 1.f / (d1 + 1e-8f);
    float r2 = 1.f / (d2 + 1e-8f);
    return fmaf(r0, f[0], fmaf(r1, f[1], r2 * f[2])) / (r0 + r1 + r2);
}

// ---------------- fused main kernel ---------------------------------------------
// grid = 512 blocks; with <=64 regs 4 blocks/SM: entire grid in one wave
__global__ void __launch_bounds__(NT, 4)
fused_kernel(const float* __restrict__ pts, float* __restrict__ out) {
    __shared__ float2 s_m[QPB * PARTS * 3];      // 12 KB merge scratch

    const int tid   = threadIdx.x;
    const int qslot = tid & 31;                  // lane
    const int part  = tid >> 5;                  // warp id == candidate part
    const int b     = (blockIdx.x * QPB) >> 13;  // batch

    u64 c2x[Q], c2y[Q], c2z[Q], qq2[Q];
#pragma unroll
    for (int j = 0; j < Q; j++) {
        int gq = blockIdx.x * QPB + 2 * qslot + j;
        float x = pts[3 * gq + 0];
        float y = pts[3 * gq + 1];
        float z = pts[3 * gq + 2];
        float qq = __fadd_rn(__fadd_rn(__fmul_rn(x, x), __fmul_rn(y, y)),
                             __fmul_rn(z, z));
        c2x[j] = dup2(-2.f * x);
        c2y[j] = dup2(-2.f * y);
        c2z[j] = dup2(-2.f * z);
        qq2[j] = dup2(qq);
    }

    float pred = 0.f;                            // meaningful for tid < QPB
    float t[Q][3], f[Q][3];

    const float* sb[3]  = { g2buf, g3buf, g4buf };
    const float* sfv[3] = { fv2buf, fv3buf, fv4buf };
    const int    sM[3]  = { M2, M3, M4 };

#pragma unroll 1
    for (int s = 0; s < 3; s++) {
        const int Mg = sM[s] / (4 * PARTS);      // groups per part
        const int grp0 = (b * sM[s]) / 4 + part * Mg;
        scan_set(sb[s], sfv[s], grp0, Mg, c2x, c2y, c2z, qq2, t, f);
#pragma unroll
        for (int j = 0; j < Q; j++) {
            int q = 2 * qslot + j;
            int bse = (q * PARTS + part) * 3;
            s_m[bse + 0] = make_float2(t[j][0], f[j][0]);
            s_m[bse + 1] = make_float2(t[j][1], f[j][1]);
            s_m[bse + 2] = make_float2(t[j][2], f[j][2]);
        }
        __syncthreads();
        if (tid < QPB) pred += merge_one(s_m + tid * PARTS * 3);
        __syncthreads();
    }

    bool found[Q];
    {
        const int Mg = MM / (4 * PARTS);
        const int grp0 = (b * MM) / 4 + part * Mg;
        scan_mask(gmbuf, grp0, Mg, c2x, c2y, c2z, qq2, found);
    }

    float* s_fl = reinterpret_cast<float*>(s_m);
#pragma unroll
    for (int j = 0; j < Q; j++)
        s_fl[(2 * qslot + j) * PARTS + part] = found[j] ? 1.f : 0.f;
    __syncthreads();
    if (tid < QPB) {
        float fl = 0.f;
#pragma unroll
        for (int k = 0; k < PARTS; k++) fl = fmaxf(fl, s_fl[tid * PARTS + k]);
        int gq = blockIdx.x * QPB + tid;
        out[gq] = pred;                          // pred_hm (B,N,1)
        out[Bn * Nn + gq] = fl;                  // gt_hm   (B,N)
    }
}

// ---------------- launch ----------------------------------------------------------
extern "C" void kernel_launch(void* const* d_in, const int* in_sizes, int n_in,
                              void* d_out, int out_size) {
    (void)in_sizes; (void)n_in; (void)out_size;
    const float* pts    = (const float*)d_in[0];
    const float* known2 = (const float*)d_in[1];
    const float* feats2 = (const float*)d_in[2];
    const float* known3 = (const float*)d_in[3];
    const float* feats3 = (const float*)d_in[4];
    const float* known4 = (const float*)d_in[5];
    const float* feats4 = (const float*)d_in[6];
    const float* matchp = (const float*)d_in[7];
    const float* w_fc   = (const float*)d_in[8];
    const float* w_cls  = (const float*)d_in[9];
    float* out = (float*)d_out;

    constexpr int total = Bn * (M2 + M3 + M4 + MM);
    precompute_kernel<<<(total + NT - 1) / NT, NT>>>(
        known2, feats2, known3, feats3, known4, feats4, matchp, w_fc, w_cls);
    fused_kernel<<<(Bn * Nn) / QPB, NT>>>(pts, out);
}